// round 1
// baseline (speedup 1.0000x reference)
#include <cuda_runtime.h>
#include <math.h>

#define NN 100000
#define NE 1600000
#define ESL (NE + NN)
#define NGRAPH 64
#define NEG 0.2f

// ---------------- scratch (device globals; no allocation) ----------------
__device__ float    d_cnt[NN];
__device__ float    d_mean[NN * 8];
__device__ float    d_xp[NN * 64];
__device__ float    d_als[NN * 4];
__device__ float    d_ald[NN * 4];
__device__ float    d_alpha[(size_t)ESL * 4];
__device__ unsigned d_m[NN * 4];
__device__ float    d_den[NN * 4];
__device__ float    d_h0[NN * 64];
__device__ float    d_h1[NN * 64];
__device__ float    d_pool[NGRAPH * 64];
__device__ float    d_gcnt[NGRAPH];
__device__ float    d_weatt[32];

// ---------------- helpers ----------------
__device__ __forceinline__ unsigned fenc(float f) {
    unsigned u = __float_as_uint(f);
    return (u & 0x80000000u) ? ~u : (u | 0x80000000u);
}
__device__ __forceinline__ float fdec(unsigned u) {
    return (u & 0x80000000u) ? __uint_as_float(u & 0x7fffffffu) : __uint_as_float(~u);
}
// Blackwell vectorized reduction (no return): one L2 RMW for 8 bytes.
__device__ __forceinline__ void red2(float* p, float a, float b) {
    asm volatile("red.global.add.v2.f32 [%0], {%1, %2};" :: "l"(p), "f"(a), "f"(b) : "memory");
}

// ---------------- self-loop mean edge-attr ----------------
__global__ void k_count(const int* __restrict__ dst, const float* __restrict__ ea) {
    int e = blockIdx.x * blockDim.x + threadIdx.x;
    if (e >= NE) return;
    int dd = dst[e];
    atomicAdd(&d_cnt[dd], 1.0f);
#pragma unroll
    for (int d = 0; d < 8; d += 2)
        red2(&d_mean[dd * 8 + d], ea[(size_t)e * 8 + d], ea[(size_t)e * 8 + d + 1]);
}

__global__ void k_meandiv() {
    int i = blockIdx.x * blockDim.x + threadIdx.x;
    if (i >= NN * 8) return;
    d_mean[i] = d_mean[i] / fmaxf(d_cnt[i >> 3], 1.0f);
}

// ---------------- per-layer edge-attention weight: weatt[d][h] = sum_c We[d, h*16+c]*ae[h,c]
__global__ void k_weatt(const float* __restrict__ We, const float* __restrict__ ae) {
    int t = threadIdx.x;
    if (t >= 32) return;
    int d = t >> 2, h = t & 3;
    float s = 0.0f;
#pragma unroll
    for (int c = 0; c < 16; c++) s += We[d * 64 + h * 16 + c] * ae[h * 16 + c];
    d_weatt[d * 4 + h] = s;
}

// ---------------- projection: xp = X @ W ; al_s/al_d per (node, head) ----------------
__global__ void k_project(const float* __restrict__ X, int fin, const float* __restrict__ W,
                          const float* __restrict__ as_, const float* __restrict__ ad_) {
    __shared__ float sW[64 * 64];
    __shared__ float sx[4 * 64];
    __shared__ float sa[64], sd[64];
    int tid = threadIdx.x;
    for (int i = tid; i < fin * 64; i += 256) sW[i] = W[i];
    if (tid < 64) { sa[tid] = as_[tid]; sd[tid] = ad_[tid]; }
    __syncthreads();
    int slot = tid >> 6, col = tid & 63;
    for (int base = blockIdx.x * 4; base < NN; base += gridDim.x * 4) {
        int n = base + slot;
        if (n < NN && col < fin) sx[slot * 64 + col] = X[(size_t)n * fin + col];
        __syncthreads();
        if (n < NN) {
            float acc = 0.0f;
            for (int i = 0; i < fin; i++) acc += sx[slot * 64 + i] * sW[i * 64 + col];
            d_xp[(size_t)n * 64 + col] = acc;
            float ps = acc * sa[col], pd = acc * sd[col];
#pragma unroll
            for (int off = 8; off; off >>= 1) {
                ps += __shfl_xor_sync(0xffffffffu, ps, off);
                pd += __shfl_xor_sync(0xffffffffu, pd, off);
            }
            if ((col & 15) == 0) {
                int h = col >> 4;
                d_als[n * 4 + h] = ps;
                d_ald[n * 4 + h] = pd;
            }
        }
        __syncthreads();
    }
}

// ---------------- pass 1: alpha + segment max ----------------
__global__ void k_alpha(const int* __restrict__ src, const int* __restrict__ dst,
                        const float* __restrict__ ea) {
    __shared__ float sw[32];
    if (threadIdx.x < 32) sw[threadIdx.x] = d_weatt[threadIdx.x];
    __syncthreads();
    int e = blockIdx.x * blockDim.x + threadIdx.x;
    if (e >= ESL) return;
    int s, dd;
    const float* a;
    if (e < NE) { s = src[e]; dd = dst[e]; a = ea + (size_t)e * 8; }
    else        { s = dd = e - NE;         a = d_mean + (size_t)(e - NE) * 8; }
    float ale[4] = {0.f, 0.f, 0.f, 0.f};
#pragma unroll
    for (int d = 0; d < 8; d++) {
        float v = a[d];
#pragma unroll
        for (int h = 0; h < 4; h++) ale[h] += v * sw[d * 4 + h];
    }
#pragma unroll
    for (int h = 0; h < 4; h++) {
        float al = d_als[s * 4 + h] + d_ald[dd * 4 + h] + ale[h];
        al = al > 0.0f ? al : NEG * al;
        d_alpha[(size_t)e * 4 + h] = al;
        atomicMax(&d_m[dd * 4 + h], fenc(al));
    }
}

// ---------------- pass 2: denominator ----------------
__global__ void k_exp(const int* __restrict__ dst) {
    int e = blockIdx.x * blockDim.x + threadIdx.x;
    if (e >= ESL) return;
    int dd = (e < NE) ? dst[e] : e - NE;
#pragma unroll
    for (int h = 0; h < 4; h++) {
        float mm = fdec(d_m[dd * 4 + h]);
        atomicAdd(&d_den[dd * 4 + h], __expf(d_alpha[(size_t)e * 4 + h] - mm));
    }
}

// ---------------- pass 3: weighted scatter (warp per edge) ----------------
__global__ void k_scatter(const int* __restrict__ src, const int* __restrict__ dst,
                          float* __restrict__ out) {
    size_t t = (size_t)blockIdx.x * blockDim.x + threadIdx.x;
    int e = (int)(t >> 5);
    int lane = (int)(t & 31);
    if (e >= ESL) return;
    int s, dd;
    if (e < NE) { s = src[e]; dd = dst[e]; } else { s = dd = e - NE; }
    int h = lane >> 3;  // cols [2*lane, 2*lane+1] -> head = lane/8
    float al = d_alpha[(size_t)e * 4 + h];
    float mm = fdec(d_m[dd * 4 + h]);
    float dn = d_den[dd * 4 + h];
    float coef = __expf(al - mm) / (dn + 1e-16f);
    float2 v = *(const float2*)(d_xp + (size_t)s * 64 + lane * 2);
    red2(out + (size_t)dd * 64 + lane * 2, v.x * coef, v.y * coef);
}

// ---------------- bias (+relu for layer 0) ----------------
__global__ void k_bias(float* __restrict__ h, const float* __restrict__ b, int dorelu) {
    size_t i = (size_t)blockIdx.x * blockDim.x + threadIdx.x;
    if (i >= (size_t)NN * 64) return;
    float v = h[i] + b[i & 63];
    if (dorelu) v = fmaxf(v, 0.0f);
    h[i] = v;
}

// ---------------- global mean pool ----------------
__global__ void k_pool(const int* __restrict__ batch, const float* __restrict__ h) {
    size_t t = (size_t)blockIdx.x * blockDim.x + threadIdx.x;
    int n = (int)(t >> 5);
    if (n >= NN) return;
    int c2 = (int)(t & 31) * 2;
    int g = batch[n];
    red2(&d_pool[g * 64 + c2], h[(size_t)n * 64 + c2], h[(size_t)n * 64 + c2 + 1]);
    if (c2 == 0) atomicAdd(&d_gcnt[g], 1.0f);
}

// ---------------- MLP head ----------------
__global__ void k_mlp(const float* __restrict__ fc1w, const float* __restrict__ fc1b,
                      const float* __restrict__ fc2w, const float* __restrict__ fc2b,
                      float* __restrict__ out) {
    int g = threadIdx.x;
    if (g >= NGRAPH) return;
    float ic = 1.0f / fmaxf(d_gcnt[g], 1.0f);
    float hr[64];
#pragma unroll
    for (int c = 0; c < 64; c++) hr[c] = d_pool[g * 64 + c] * ic;
    float y1[32];
#pragma unroll
    for (int j = 0; j < 32; j++) {
        float s = fc1b[j];
#pragma unroll
        for (int c = 0; c < 64; c++) s += hr[c] * fc1w[c * 32 + j];
        y1[j] = fmaxf(s, 0.0f);
    }
#pragma unroll
    for (int o = 0; o < 2; o++) {
        float s = fc2b[o];
#pragma unroll
        for (int j = 0; j < 32; j++) s += y1[j] * fc2w[j * 2 + o];
        out[g * 2 + o] = s;
    }
}

// ---------------- host ----------------
extern "C" void kernel_launch(void* const* d_in, const int* in_sizes, int n_in,
                              void* d_out, int out_size) {
    (void)in_sizes; (void)n_in; (void)out_size;
    const float* x    = (const float*)d_in[0];
    const int*   ei   = (const int*)d_in[1];    // int32 (JAX x64 disabled demotes int64)
    const float* ea   = (const float*)d_in[2];
    const int*   batch= (const int*)d_in[3];
    const float* W0   = (const float*)d_in[4];
    const float* as0  = (const float*)d_in[5];
    const float* ad0  = (const float*)d_in[6];
    const float* We0  = (const float*)d_in[7];
    const float* ae0  = (const float*)d_in[8];
    const float* b0   = (const float*)d_in[9];
    const float* Wh   = (const float*)d_in[10];
    const float* ash  = (const float*)d_in[11];
    const float* adh  = (const float*)d_in[12];
    const float* Weh  = (const float*)d_in[13];
    const float* aeh  = (const float*)d_in[14];
    const float* bh   = (const float*)d_in[15];
    const float* fc1w = (const float*)d_in[16];
    const float* fc1b = (const float*)d_in[17];
    const float* fc2w = (const float*)d_in[18];
    const float* fc2b = (const float*)d_in[19];
    float* out = (float*)d_out;

    const int* src = ei;
    const int* dst = ei + NE;

    void *p_cnt, *p_mean, *p_m, *p_den, *p_h0, *p_h1, *p_pool, *p_gcnt;
    cudaGetSymbolAddress(&p_cnt,  d_cnt);
    cudaGetSymbolAddress(&p_mean, d_mean);
    cudaGetSymbolAddress(&p_m,    d_m);
    cudaGetSymbolAddress(&p_den,  d_den);
    cudaGetSymbolAddress(&p_h0,   d_h0);
    cudaGetSymbolAddress(&p_h1,   d_h1);
    cudaGetSymbolAddress(&p_pool, d_pool);
    cudaGetSymbolAddress(&p_gcnt, d_gcnt);

    // self-loop mean edge attrs (shared across layers)
    cudaMemsetAsync(p_cnt, 0, NN * sizeof(float));
    cudaMemsetAsync(p_mean, 0, NN * 8 * sizeof(float));
    k_count<<<(NE + 255) / 256, 256>>>(dst, ea);
    k_meandiv<<<(NN * 8 + 255) / 256, 256>>>();

    struct LayerCfg {
        const float* X; int fin; const float* W;
        const float* as; const float* ad; const float* We; const float* ae;
        const float* b; float* hout; int relu;
    };
    LayerCfg L[3] = {
        { x,            32, W0,        as0,      ad0,      We0,       ae0,      b0,      (float*)p_h0, 1 },
        { (float*)p_h0, 64, Wh,        ash,      adh,      Weh,       aeh,      bh,      (float*)p_h1, 0 },
        { (float*)p_h1, 64, Wh + 4096, ash + 64, adh + 64, Weh + 512, aeh + 64, bh + 64, (float*)p_h0, 0 },
    };

    const int gridE = (ESL + 255) / 256;
    for (int l = 0; l < 3; l++) {
        cudaMemsetAsync(p_m,   0, NN * 4 * sizeof(unsigned));
        cudaMemsetAsync(p_den, 0, NN * 4 * sizeof(float));
        cudaMemsetAsync(L[l].hout, 0, (size_t)NN * 64 * sizeof(float));
        k_weatt<<<1, 32>>>(L[l].We, L[l].ae);
        k_project<<<1184, 256>>>(L[l].X, L[l].fin, L[l].W, L[l].as, L[l].ad);
        k_alpha<<<gridE, 256>>>(src, dst, ea);
        k_exp<<<gridE, 256>>>(dst);
        k_scatter<<<(int)(((size_t)ESL * 32 + 255) / 256), 256>>>(src, dst, L[l].hout);
        k_bias<<<(NN * 64 + 255) / 256, 256>>>(L[l].hout, L[l].b, L[l].relu);
    }

    cudaMemsetAsync(p_pool, 0, NGRAPH * 64 * sizeof(float));
    cudaMemsetAsync(p_gcnt, 0, NGRAPH * sizeof(float));
    k_pool<<<(int)(((size_t)NN * 32 + 255) / 256), 256>>>(batch, (const float*)p_h0);
    k_mlp<<<1, 64>>>(fc1w, fc1b, fc2w, fc2b, out);
}